// round 1
// baseline (speedup 1.0000x reference)
#include <cuda_runtime.h>
#include <math.h>

#define NC 2048
#define DIN 512
#define DH 1024
#define DO 512
#define GIN 1537
#define LDCM 1552          // padded stride for K=1537 matrices (mult of 16)
#define KENG 2048

// ---------------- scratch (device globals: allowed, no runtime alloc) ----------------
__device__ float g_Acat[NC * 2048];       // [h_re | h_im]
__device__ float g_Bre[2048 * DO];        // [Wrd_bot ; -Wid_bot]
__device__ float g_Bim[2048 * DO];        // [Wid_bot ;  Wrd_bot]
__device__ float g_vre[DO];
__device__ float g_vim[DO];
__device__ float g_ore[NC * DO];
__device__ float g_oim[NC * DO];
__device__ float g_t[NC];
__device__ float g_stats[2];              // softmax max, denom
__device__ float g_cm[NC * LDCM];
__device__ float g_cr[NC * LDCM];
__device__ float g_ci[NC * LDCM];
__device__ float g_z[NC * DH];
__device__ float g_rr[NC * DH];
__device__ float g_nre[NC * DH];
__device__ float g_nim[NC * DH];
__device__ float g_fm[2 * 8 * DH];
__device__ float g_gm[2 * DH];
__device__ float g_cv[2 * DO];            // weighted [comb_re | comb_im]

// ---------------- prep kernels ----------------
__global__ void prep_engineB(const float* __restrict__ ea_wr, const float* __restrict__ ea_wi,
                             const float* __restrict__ eg_wr, const float* __restrict__ eg_wi) {
    int idx = blockIdx.x * 256 + threadIdx.x;   // 2048*512
    int k = idx >> 9;
    int j = idx & 511;
    if (k < 1024) {
        int r = (512 + k) * 512 + j;
        g_Bre[idx] = ea_wr[r] - eg_wr[r];
        g_Bim[idx] = ea_wi[r] - eg_wi[r];
    } else {
        int r = (512 + (k - 1024)) * 512 + j;
        g_Bre[idx] = -(ea_wi[r] - eg_wi[r]);
        g_Bim[idx] = ea_wr[r] - eg_wr[r];
    }
}

__global__ void prep_vec(const float* __restrict__ x,
                         const float* __restrict__ ea_wr, const float* __restrict__ ea_br,
                         const float* __restrict__ ea_wi, const float* __restrict__ ea_bi,
                         const float* __restrict__ eg_wr, const float* __restrict__ eg_br,
                         const float* __restrict__ eg_wi, const float* __restrict__ eg_bi) {
    int j = blockIdx.x;
    int tid = threadIdx.x;   // 128
    float sr = 0.f, si = 0.f;
    for (int k = tid; k < 512; k += 128) {
        float xv = x[k];
        int r = k * 512 + j;
        sr += xv * (ea_wr[r] - eg_wr[r]);
        si += xv * (ea_wi[r] - eg_wi[r]);
    }
    __shared__ float shr[128], shi[128];
    shr[tid] = sr; shi[tid] = si;
    __syncthreads();
    for (int s = 64; s > 0; s >>= 1) {
        if (tid < s) { shr[tid] += shr[tid + s]; shi[tid] += shi[tid + s]; }
        __syncthreads();
    }
    if (tid == 0) {
        g_vre[j] = shr[0] + ea_br[j] - ea_bi[j] - eg_br[j] + eg_bi[j];
        g_vim[j] = shi[0] + ea_br[j] + ea_bi[j] - eg_br[j] - eg_bi[j];
    }
}

__global__ void prep_acat(const float* __restrict__ h_re, const float* __restrict__ h_im) {
    int idx = blockIdx.x * 256 + threadIdx.x;  // 2048*512 float4 slots
    int n = idx >> 9;
    int k = (idx & 511) * 4;
    float4 v;
    if (k < 1024) v = *reinterpret_cast<const float4*>(h_re + n * 1024 + k);
    else          v = *reinterpret_cast<const float4*>(h_im + n * 1024 + (k - 1024));
    *reinterpret_cast<float4*>(g_Acat + n * 2048 + k) = v;
}

// ---------------- GEMM: C[M,N] = A[M,K] @ B[K,N]  (+ epilogue) ----------------
// BM=128, BN=64, BK=16, 256 threads, 8x4 micro-tile, global-load prefetch.
// EPI: 0 -> C = acc + vec[n]
//      1 -> C = sigmoid(acc + vec[n])
//      2 -> cand = tanh(acc + vec[n]); C = (1-Z)*H + Z*cand
template<int EPI>
__global__ void __launch_bounds__(256, 1) gemm_k(
    const float* __restrict__ A, int lda,
    const float* __restrict__ B, int ldb, int K,
    float* __restrict__ C, int ldc,
    const float* __restrict__ vec,
    const float* __restrict__ Zp,
    const float* __restrict__ Hp)
{
    __shared__ float As[16][132];
    __shared__ float Bs[16][64];
    const int tid = threadIdx.x;
    const int bm = blockIdx.y * 128;
    const int bn = blockIdx.x * 64;
    const int tx = tid & 15;
    const int ty = tid >> 4;

    const int ar = tid >> 2;          // 0..63
    const int ac = (tid & 3) * 4;     // 0,4,8,12
    const int br = tid >> 4;          // 0..15
    const int bc = (tid & 15) * 4;

    float acc[8][4];
#pragma unroll
    for (int i = 0; i < 8; i++)
#pragma unroll
        for (int j = 0; j < 4; j++) acc[i][j] = 0.f;

    const float* Ap0 = A + (size_t)(bm + ar) * lda + ac;
    const float* Ap1 = A + (size_t)(bm + ar + 64) * lda + ac;

    float4 a0r, a1r, b0r;
    {   // prefetch tile 0
        a0r = *reinterpret_cast<const float4*>(Ap0);
        a1r = *reinterpret_cast<const float4*>(Ap1);
        int kg = br;
        b0r = (kg < K) ? *reinterpret_cast<const float4*>(B + (size_t)kg * ldb + bn + bc)
                       : make_float4(0.f, 0.f, 0.f, 0.f);
    }

    for (int kt = 0; kt < K; kt += 16) {
        As[ac + 0][ar] = a0r.x; As[ac + 1][ar] = a0r.y; As[ac + 2][ar] = a0r.z; As[ac + 3][ar] = a0r.w;
        As[ac + 0][ar + 64] = a1r.x; As[ac + 1][ar + 64] = a1r.y; As[ac + 2][ar + 64] = a1r.z; As[ac + 3][ar + 64] = a1r.w;
        *reinterpret_cast<float4*>(&Bs[br][bc]) = b0r;
        __syncthreads();

        int kn = kt + 16;
        if (kn < K) {   // prefetch next tile while computing this one
            a0r = *reinterpret_cast<const float4*>(Ap0 + kn);
            a1r = *reinterpret_cast<const float4*>(Ap1 + kn);
            int kg = kn + br;
            b0r = (kg < K) ? *reinterpret_cast<const float4*>(B + (size_t)kg * ldb + bn + bc)
                           : make_float4(0.f, 0.f, 0.f, 0.f);
        }

#pragma unroll
        for (int k = 0; k < 16; k++) {
            const float4 av0 = *reinterpret_cast<const float4*>(&As[k][ty * 8]);
            const float4 av1 = *reinterpret_cast<const float4*>(&As[k][ty * 8 + 4]);
            const float4 bv  = *reinterpret_cast<const float4*>(&Bs[k][tx * 4]);
            float am[8] = {av0.x, av0.y, av0.z, av0.w, av1.x, av1.y, av1.z, av1.w};
            float bb[4] = {bv.x, bv.y, bv.z, bv.w};
#pragma unroll
            for (int i = 0; i < 8; i++)
#pragma unroll
                for (int j = 0; j < 4; j++) acc[i][j] += am[i] * bb[j];
        }
        __syncthreads();
    }

#pragma unroll
    for (int i = 0; i < 8; i++) {
        int m = bm + ty * 8 + i;
#pragma unroll
        for (int j = 0; j < 4; j++) {
            int n = bn + tx * 4 + j;
            float v = acc[i][j] + vec[n];
            if (EPI == 1) v = 1.f / (1.f + expf(-v));
            if (EPI == 2) {
                float cand = tanhf(v);
                float zz = Zp[(size_t)m * ldc + n];
                float hh = Hp[(size_t)m * ldc + n];
                v = (1.f - zz) * hh + zz * cand;
            }
            C[(size_t)m * ldc + n] = v;
        }
    }
}

// ---------------- elementwise / reductions ----------------
__global__ void tension_k() {
    int n = blockIdx.x;
    int tid = threadIdx.x;   // 128
    float s = 0.f;
    for (int j = tid; j < 512; j += 128) {
        float a = g_ore[n * 512 + j], b = g_oim[n * 512 + j];
        s += a * a + b * b;
    }
    __shared__ float sh[128];
    sh[tid] = s; __syncthreads();
    for (int st = 64; st > 0; st >>= 1) {
        if (tid < st) sh[tid] += sh[tid + st];
        __syncthreads();
    }
    if (tid == 0) g_t[n] = sh[0] * (1.f / 512.f);
}

__global__ void stats_k(float* __restrict__ out) {   // 1 block, 1024 threads
    int tid = threadIdx.x;
    float t0 = g_t[tid], t1 = g_t[tid + 1024];
    __shared__ float sh[1024];
    sh[tid] = fmaxf(t0, t1); __syncthreads();
    for (int s = 512; s > 0; s >>= 1) {
        if (tid < s) sh[tid] = fmaxf(sh[tid], sh[tid + s]);
        __syncthreads();
    }
    float mx = sh[0]; __syncthreads();
    sh[tid] = expf(t0 - mx) + expf(t1 - mx); __syncthreads();
    for (int s = 512; s > 0; s >>= 1) {
        if (tid < s) sh[tid] += sh[tid + s];
        __syncthreads();
    }
    float denom = sh[0]; __syncthreads();
    sh[tid] = t0 + t1; __syncthreads();
    for (int s = 512; s > 0; s >>= 1) {
        if (tid < s) sh[tid] += sh[tid + s];
        __syncthreads();
    }
    if (tid == 0) {
        g_stats[0] = mx;
        g_stats[1] = denom;
        out[512] = sh[0] * (1.f / 2048.f);  // mean tension
    }
    g_cv[tid] = 0.f;   // zero the weighted-sum accumulator (1024 entries)
}

__global__ void build_cm(const float* __restrict__ h_re, const float* __restrict__ h_im) {
    int idx = blockIdx.x * 256 + threadIdx.x;   // NC * LDCM
    int n = idx / LDCM;
    int j = idx - n * LDCM;
    float v;
    if (j < 512) {
        float a = g_ore[n * 512 + j], b = g_oim[n * 512 + j];
        v = sqrtf(a * a + b * b);
    } else if (j == 512) {
        v = g_t[n];                               // sqrt(t^2 + 0) = t  (t >= 0)
    } else if (j < GIN) {
        int jj = j - 513;
        float a = h_re[n * 1024 + jj], b = h_im[n * 1024 + jj];
        v = sqrtf(a * a + b * b);
    } else v = 0.f;
    g_cm[idx] = v;
}

__global__ void build_comb(const float* __restrict__ h_re, const float* __restrict__ h_im) {
    int idx = blockIdx.x * 256 + threadIdx.x;   // NC * LDCM
    int n = idx / LDCM;
    int j = idx - n * LDCM;
    float cr, ci;
    if (j < 512) {
        cr = g_ore[n * 512 + j]; ci = g_oim[n * 512 + j];
    } else if (j == 512) {
        cr = g_t[n]; ci = 0.f;
    } else if (j < GIN) {
        int jj = j - 513;
        float rv = g_rr[n * 1024 + jj];
        cr = rv * h_re[n * 1024 + jj];
        ci = rv * h_im[n * 1024 + jj];
    } else { cr = 0.f; ci = 0.f; }
    g_cr[idx] = cr;
    g_ci[idx] = ci;
}

__global__ void fmean_k() {   // grid 16 (comp*8+f), block 1024 (d)
    int b = blockIdx.x;
    int comp = b >> 3, f = b & 7, d = threadIdx.x;
    const float* src = comp ? g_nim : g_nre;
    float s = 0.f;
    for (int i = 0; i < 256; i++) s += src[(f * 256 + i) * 1024 + d];
    g_fm[(comp * 8 + f) * 1024 + d] = s * (1.f / 256.f);
}

__global__ void gmean_k() {   // grid 2, block 1024
    int comp = blockIdx.x, d = threadIdx.x;
    float s = 0.f;
    for (int f = 0; f < 8; f++) s += g_fm[(comp * 8 + f) * 1024 + d];
    g_gm[comp * 1024 + d] = s * 0.125f;
}

__global__ void apply_sync(float* __restrict__ out, const int* __restrict__ step) {
    int idx = blockIdx.x * 256 + threadIdx.x;   // 2 * 2048 * 1024
    int comp = idx >> 21;
    int rem = idx & ((1 << 21) - 1);
    int n = rem >> 10, d = rem & 1023;
    const float* src = comp ? g_nim : g_nre;
    float v = src[rem];
    int f = n >> 8;
    v = 0.85f * v + 0.15f * g_fm[(comp * 8 + f) * 1024 + d];
    if (step[0] > 5 && (n & 255) < 64)
        v = 0.85f * v + 0.15f * g_gm[comp * 1024 + d];
    out[513 + idx] = v;
}

__global__ void wsum_k() {   // grid 64 (32-row chunks), block 256
    int blk = blockIdx.x, tid = threadIdx.x;
    float mx = g_stats[0];
    float inv = 1.f / g_stats[1];
    float a0 = 0.f, a1 = 0.f, a2 = 0.f, a3 = 0.f;
    for (int i = 0; i < 32; i++) {
        int n = blk * 32 + i;
        float w = expf(g_t[n] - mx) * inv;
        a0 += w * g_ore[n * 512 + tid];
        a1 += w * g_ore[n * 512 + 256 + tid];
        a2 += w * g_oim[n * 512 + tid];
        a3 += w * g_oim[n * 512 + 256 + tid];
    }
    atomicAdd(&g_cv[tid], a0);
    atomicAdd(&g_cv[256 + tid], a1);
    atomicAdd(&g_cv[512 + tid], a2);
    atomicAdd(&g_cv[768 + tid], a3);
}

__global__ void pred_k(const float* __restrict__ oh_w, const float* __restrict__ oh_b,
                       float* __restrict__ out) {   // grid 2, block 256
    int j = blockIdx.x * 256 + threadIdx.x;   // 0..511
    float acc = 0.f;
    for (int k = 0; k < 1024; k++) acc += g_cv[k] * oh_w[k * 512 + j];
    out[j] = acc + oh_b[j];
}

// ---------------- launch ----------------
extern "C" void kernel_launch(void* const* d_in, const int* in_sizes, int n_in,
                              void* d_out, int out_size) {
    (void)in_sizes; (void)n_in; (void)out_size;
    const float* x     = (const float*)d_in[0];
    const float* h_re  = (const float*)d_in[1];
    const float* h_im  = (const float*)d_in[2];
    const float* ea_wr = (const float*)d_in[3];
    const float* ea_br = (const float*)d_in[4];
    const float* ea_wi = (const float*)d_in[5];
    const float* ea_bi = (const float*)d_in[6];
    const float* eg_wr = (const float*)d_in[7];
    const float* eg_br = (const float*)d_in[8];
    const float* eg_wi = (const float*)d_in[9];
    const float* eg_bi = (const float*)d_in[10];
    const float* gz_w  = (const float*)d_in[11];
    const float* gz_b  = (const float*)d_in[12];
    const float* gr_w  = (const float*)d_in[13];
    const float* gr_b  = (const float*)d_in[14];
    const float* ghr_w = (const float*)d_in[15];
    const float* ghr_b = (const float*)d_in[16];
    const float* ghi_w = (const float*)d_in[17];
    const float* ghi_b = (const float*)d_in[18];
    const float* oh_w  = (const float*)d_in[19];
    const float* oh_b  = (const float*)d_in[20];
    const int*   step  = (const int*)d_in[21];
    float* out = (float*)d_out;

    // scratch addresses (symbol lookup: no stream work, capture-safe)
    float *pAcat, *pBre, *pBim, *pVre, *pVim, *pOre, *pOim, *pCm, *pCr, *pCi, *pZ, *pR, *pNre, *pNim;
    cudaGetSymbolAddress((void**)&pAcat, g_Acat);
    cudaGetSymbolAddress((void**)&pBre,  g_Bre);
    cudaGetSymbolAddress((void**)&pBim,  g_Bim);
    cudaGetSymbolAddress((void**)&pVre,  g_vre);
    cudaGetSymbolAddress((void**)&pVim,  g_vim);
    cudaGetSymbolAddress((void**)&pOre,  g_ore);
    cudaGetSymbolAddress((void**)&pOim,  g_oim);
    cudaGetSymbolAddress((void**)&pCm,   g_cm);
    cudaGetSymbolAddress((void**)&pCr,   g_cr);
    cudaGetSymbolAddress((void**)&pCi,   g_ci);
    cudaGetSymbolAddress((void**)&pZ,    g_z);
    cudaGetSymbolAddress((void**)&pR,    g_rr);
    cudaGetSymbolAddress((void**)&pNre,  g_nre);
    cudaGetSymbolAddress((void**)&pNim,  g_nim);

    prep_engineB<<<4096, 256>>>(ea_wr, ea_wi, eg_wr, eg_wi);
    prep_vec<<<512, 128>>>(x, ea_wr, ea_br, ea_wi, ea_bi, eg_wr, eg_br, eg_wi, eg_bi);
    prep_acat<<<4096, 256>>>(h_re, h_im);

    // engine: o_re / o_im
    gemm_k<0><<<dim3(8, 16), 256>>>(pAcat, 2048, pBre, 512, KENG, pOre, 512, pVre, nullptr, nullptr);
    gemm_k<0><<<dim3(8, 16), 256>>>(pAcat, 2048, pBim, 512, KENG, pOim, 512, pVim, nullptr, nullptr);

    tension_k<<<2048, 128>>>();
    stats_k<<<1, 1024>>>(out);

    build_cm<<<12416, 256>>>(h_re, h_im);
    gemm_k<1><<<dim3(16, 16), 256>>>(pCm, LDCM, gz_w, 1024, GIN, pZ, 1024, gz_b, nullptr, nullptr);
    gemm_k<1><<<dim3(16, 16), 256>>>(pCm, LDCM, gr_w, 1024, GIN, pR, 1024, gr_b, nullptr, nullptr);

    build_comb<<<12416, 256>>>(h_re, h_im);
    gemm_k<2><<<dim3(16, 16), 256>>>(pCr, LDCM, ghr_w, 1024, GIN, pNre, 1024, ghr_b, pZ, h_re);
    gemm_k<2><<<dim3(16, 16), 256>>>(pCi, LDCM, ghi_w, 1024, GIN, pNim, 1024, ghi_b, pZ, h_im);

    fmean_k<<<16, 1024>>>();
    gmean_k<<<2, 1024>>>();
    apply_sync<<<16384, 256>>>(out, step);

    wsum_k<<<64, 256>>>();
    pred_k<<<2, 256>>>(oh_w, oh_b, out);
}

// round 3
// speedup vs baseline: 1.2000x; 1.2000x over previous
#include <cuda_runtime.h>
#include <cuda_bf16.h>
#include <cstdint>
#include <math.h>

#define NC 2048
#define DH 1024
#define DO 512
#define GIN 1537
#define LDT 1600           // GRU K padded to multiple of 64
#define KENG 2048

// ---------------- scratch ----------------
__device__ float g_BreT[DO * KENG];       // engine B^T (re), [N][K]
__device__ float g_BimT[DO * KENG];       // engine B^T (im)
__device__ float g_WT[4][DH * LDT];       // gz, gr, ghr, ghi transposed [1024][1600]
__device__ float g_vre[DO];
__device__ float g_vim[DO];
__device__ float g_ore[NC * DO];
__device__ float g_oim[NC * DO];
__device__ float g_t[NC];
__device__ float g_stats[2];
__device__ float g_cm[NC * LDT];
__device__ float g_cr[NC * LDT];
__device__ float g_ci[NC * LDT];
__device__ float g_z[NC * DH];
__device__ float g_rr[NC * DH];
__device__ float g_nre[NC * DH];
__device__ float g_nim[NC * DH];
__device__ float g_fm[2 * 8 * DH];
__device__ float g_gm[2 * DH];
__device__ float g_cv[2 * DO];

// ---------------- helpers ----------------
__device__ __forceinline__ uint32_t smem_u32(const void* p) {
    uint32_t a;
    asm("{ .reg .u64 t; cvta.to.shared.u64 t, %1; cvt.u32.u64 %0, t; }" : "=r"(a) : "l"(p));
    return a;
}
__device__ __forceinline__ void ldsm4(uint32_t* r, uint32_t addr) {
    asm volatile("ldmatrix.sync.aligned.m8n8.x4.shared.b16 {%0,%1,%2,%3}, [%4];"
                 : "=r"(r[0]), "=r"(r[1]), "=r"(r[2]), "=r"(r[3]) : "r"(addr));
}
__device__ __forceinline__ void mma_bf16(float* d, const uint32_t* a, const uint32_t* b) {
    asm volatile("mma.sync.aligned.m16n8k16.row.col.f32.bf16.bf16.f32 "
                 "{%0,%1,%2,%3}, {%4,%5,%6,%7}, {%8,%9}, {%0,%1,%2,%3};"
                 : "+f"(d[0]), "+f"(d[1]), "+f"(d[2]), "+f"(d[3])
                 : "r"(a[0]), "r"(a[1]), "r"(a[2]), "r"(a[3]), "r"(b[0]), "r"(b[1]));
}
__device__ __forceinline__ void split4(float4 v, uint2& h, uint2& l) {
    __nv_bfloat16 bx = __float2bfloat16_rn(v.x);
    __nv_bfloat16 by = __float2bfloat16_rn(v.y);
    __nv_bfloat16 bz = __float2bfloat16_rn(v.z);
    __nv_bfloat16 bw = __float2bfloat16_rn(v.w);
    __nv_bfloat162 h0; h0.x = bx; h0.y = by;
    __nv_bfloat162 h1; h1.x = bz; h1.y = bw;
    h.x = *reinterpret_cast<const uint32_t*>(&h0);
    h.y = *reinterpret_cast<const uint32_t*>(&h1);
    __nv_bfloat16 lx = __float2bfloat16_rn(v.x - __bfloat162float(bx));
    __nv_bfloat16 ly = __float2bfloat16_rn(v.y - __bfloat162float(by));
    __nv_bfloat16 lz = __float2bfloat16_rn(v.z - __bfloat162float(bz));
    __nv_bfloat16 lw = __float2bfloat16_rn(v.w - __bfloat162float(bw));
    __nv_bfloat162 l0; l0.x = lx; l0.y = ly;
    __nv_bfloat162 l1; l1.x = lz; l1.y = lw;
    l.x = *reinterpret_cast<const uint32_t*>(&l0);
    l.y = *reinterpret_cast<const uint32_t*>(&l1);
}

// ---------------- prep kernels ----------------
__global__ void prep_vec(const float* __restrict__ x,
                         const float* __restrict__ ea_wr, const float* __restrict__ ea_br,
                         const float* __restrict__ ea_wi, const float* __restrict__ ea_bi,
                         const float* __restrict__ eg_wr, const float* __restrict__ eg_br,
                         const float* __restrict__ eg_wi, const float* __restrict__ eg_bi) {
    int j = blockIdx.x;
    int tid = threadIdx.x;
    float sr = 0.f, si = 0.f;
    for (int k = tid; k < 512; k += 128) {
        float xv = x[k];
        int r = k * 512 + j;
        sr += xv * (ea_wr[r] - eg_wr[r]);
        si += xv * (ea_wi[r] - eg_wi[r]);
    }
    __shared__ float shr[128], shi[128];
    shr[tid] = sr; shi[tid] = si;
    __syncthreads();
    for (int s = 64; s > 0; s >>= 1) {
        if (tid < s) { shr[tid] += shr[tid + s]; shi[tid] += shi[tid + s]; }
        __syncthreads();
    }
    if (tid == 0) {
        g_vre[j] = shr[0] + ea_br[j] - ea_bi[j] - eg_br[j] + eg_bi[j];
        g_vim[j] = shi[0] + ea_br[j] + ea_bi[j] - eg_br[j] - eg_bi[j];
    }
}

// engine weight diff, transposed to [n][k]
__global__ void transpose_e(const float* __restrict__ ea_wr, const float* __restrict__ ea_wi,
                            const float* __restrict__ eg_wr, const float* __restrict__ eg_wi) {
    __shared__ float tr[32][33], ti[32][33];
    int kb = blockIdx.x * 32, nb = blockIdx.y * 32;
    int tx = threadIdx.x, ty = threadIdx.y;
    for (int i = ty; i < 32; i += 8) {
        int k = kb + i, n = nb + tx;
        float re, im;
        if (k < 1024) {
            int r = (512 + k) * 512 + n;
            re = ea_wr[r] - eg_wr[r];
            im = ea_wi[r] - eg_wi[r];
        } else {
            int r = (k - 512) * 512 + n;
            re = -(ea_wi[r] - eg_wi[r]);
            im = ea_wr[r] - eg_wr[r];
        }
        tr[i][tx] = re; ti[i][tx] = im;
    }
    __syncthreads();
    for (int i = ty; i < 32; i += 8) {
        g_BreT[(size_t)(nb + i) * KENG + kb + tx] = tr[tx][i];
        g_BimT[(size_t)(nb + i) * KENG + kb + tx] = ti[tx][i];
    }
}

// GRU weights [1537][1024] -> [1024][1600] (zero-padded K)
__global__ void transpose_w(const float* __restrict__ w0, const float* __restrict__ w1,
                            const float* __restrict__ w2, const float* __restrict__ w3) {
    __shared__ float tile[32][33];
    int z = blockIdx.z;
    const float* src = (z == 0) ? w0 : (z == 1) ? w1 : (z == 2) ? w2 : w3;
    int kb = blockIdx.x * 32, nb = blockIdx.y * 32;
    int tx = threadIdx.x, ty = threadIdx.y;
    for (int i = ty; i < 32; i += 8) {
        int k = kb + i;
        tile[i][tx] = (k < GIN) ? src[(size_t)k * 1024 + nb + tx] : 0.f;
    }
    __syncthreads();
    float* dst = g_WT[z];
    for (int i = ty; i < 32; i += 8) {
        dst[(size_t)(nb + i) * LDT + kb + tx] = tile[tx][i];
    }
}

// ---------------- mma.sync bf16 GEMM (3-term split) ----------------
// C[M,N] = A[M,K] @ BT[N,K]^T ; CTA tile 128x128, K-chunks of 64, 8 warps.
// EPI: 0 -> acc+vec ; 1 -> sigmoid(acc+vec) ; 2 -> (1-Z)*H + Z*tanh(acc+vec)
#define SMEM_GEMM_BYTES 65536
template<int EPI>
__global__ void __launch_bounds__(256, 1) gemm_mma(
    const float* __restrict__ A, const float* __restrict__ A2, int lda, int Ksplit,
    const float* __restrict__ BT, int ldb, int K,
    float* __restrict__ C, int ldc,
    const float* __restrict__ vec,
    const float* __restrict__ Zp, const float* __restrict__ Hp)
{
    extern __shared__ char smem[];
    uint32_t sb = smem_u32(smem);
    const int tid = threadIdx.x;
    const int wid = tid >> 5, l = tid & 31;
    const int wm = wid & 1, wn = wid >> 1;
    const int bm = blockIdx.y * 128;
    const int bn = blockIdx.x * 128;

    float acc[4][4][4];
#pragma unroll
    for (int a = 0; a < 4; a++)
#pragma unroll
        for (int b = 0; b < 4; b++)
#pragma unroll
            for (int c = 0; c < 4; c++) acc[a][b][c] = 0.f;

    const int lrow = tid >> 1;
    const int lseg = (tid & 1) * 32;    // element offset within 64-wide chunk
    const int NK = K >> 6;

    float4 ra[8], rb[8];
    {   // prefetch chunk 0 (kc=0 always < Ksplit)
        const float* ab = A + (size_t)(bm + lrow) * lda + lseg;
        const float* bb = BT + (size_t)(bn + lrow) * ldb + lseg;
#pragma unroll
        for (int i = 0; i < 8; i++) {
            ra[i] = *reinterpret_cast<const float4*>(ab + i * 4);
            rb[i] = *reinterpret_cast<const float4*>(bb + i * 4);
        }
    }

    const int o0 = lrow * 128 + (tid & 1) * 64;

    for (int ch = 0; ch < NK; ch++) {
        // convert + store current chunk to smem (swizzled)
#pragma unroll
        for (int i = 0; i < 8; i++) {
            int o = o0 + i * 8;
            int sw = o ^ ((o >> 3) & 0x70);
            uint2 h, lo2;
            split4(ra[i], h, lo2);
            *reinterpret_cast<uint2*>(smem + sw)          = h;    // A hi
            *reinterpret_cast<uint2*>(smem + 16384 + sw)  = lo2;  // A lo
            split4(rb[i], h, lo2);
            *reinterpret_cast<uint2*>(smem + 32768 + sw)  = h;    // B hi
            *reinterpret_cast<uint2*>(smem + 49152 + sw)  = lo2;  // B lo
        }
        __syncthreads();

        // prefetch next chunk
        if (ch + 1 < NK) {
            int kc = (ch + 1) * 64;
            const float* ab = (kc < Ksplit)
                ? A  + (size_t)(bm + lrow) * lda + kc + lseg
                : A2 + (size_t)(bm + lrow) * lda + (kc - Ksplit) + lseg;
            const float* bb = BT + (size_t)(bn + lrow) * ldb + kc + lseg;
#pragma unroll
            for (int i = 0; i < 8; i++) {
                ra[i] = *reinterpret_cast<const float4*>(ab + i * 4);
                rb[i] = *reinterpret_cast<const float4*>(bb + i * 4);
            }
        }

        // compute 4 k16-steps on this chunk
#pragma unroll
        for (int ks = 0; ks < 4; ks++) {
            uint32_t ah[4][4], al[4][4], bhq[2][4], blq[2][4];
            const int arow0 = wm * 64 + (l & 15);
            const int akb = ks * 32 + ((l >> 4) << 4);
#pragma unroll
            for (int mi = 0; mi < 4; mi++) {
                int row = arow0 + mi * 16;
                uint32_t ad = sb + row * 128 + (akb ^ ((row & 7) << 4));
                ldsm4(ah[mi], ad);
                ldsm4(al[mi], ad + 16384);
            }
            const int brow0 = wn * 32 + (l & 7) + ((l >> 4) << 3);
            const int bkb = ks * 32 + (((l >> 3) & 1) << 4);
#pragma unroll
            for (int nj = 0; nj < 2; nj++) {
                int row = brow0 + nj * 16;
                uint32_t bd = sb + 32768 + row * 128 + (bkb ^ ((row & 7) << 4));
                ldsm4(bhq[nj], bd);
                ldsm4(blq[nj], bd + 16384);
            }
#pragma unroll
            for (int mi = 0; mi < 4; mi++)
#pragma unroll
                for (int ni = 0; ni < 4; ni++) {
                    const uint32_t* bh2 = &bhq[ni >> 1][(ni & 1) * 2];
                    const uint32_t* bl2 = &blq[ni >> 1][(ni & 1) * 2];
                    mma_bf16(acc[mi][ni], ah[mi], bh2);
                    mma_bf16(acc[mi][ni], al[mi], bh2);
                    mma_bf16(acc[mi][ni], ah[mi], bl2);
                }
        }
        __syncthreads();
    }

    // epilogue
    const int mr = bm + wm * 64 + (l >> 2);
    const int nc0 = bn + wn * 32 + ((l & 3) << 1);
#pragma unroll
    for (int mi = 0; mi < 4; mi++) {
#pragma unroll
        for (int ni = 0; ni < 4; ni++) {
            int n = nc0 + ni * 8;
            float v0 = vec[n], v1 = vec[n + 1];
#pragma unroll
            for (int hh = 0; hh < 2; hh++) {
                int m = mr + mi * 16 + hh * 8;
                float e0 = acc[mi][ni][hh * 2 + 0] + v0;
                float e1 = acc[mi][ni][hh * 2 + 1] + v1;
                if (EPI == 1) {
                    e0 = 1.f / (1.f + expf(-e0));
                    e1 = 1.f / (1.f + expf(-e1));
                }
                if (EPI == 2) {
                    float c0 = tanhf(e0), c1 = tanhf(e1);
                    float z0 = Zp[(size_t)m * ldc + n], z1 = Zp[(size_t)m * ldc + n + 1];
                    float h0 = Hp[(size_t)m * ldc + n], h1 = Hp[(size_t)m * ldc + n + 1];
                    e0 = (1.f - z0) * h0 + z0 * c0;
                    e1 = (1.f - z1) * h1 + z1 * c1;
                }
                float2 o; o.x = e0; o.y = e1;
                *reinterpret_cast<float2*>(C + (size_t)m * ldc + n) = o;
            }
        }
    }
}

// ---------------- elementwise / reductions ----------------
__global__ void tension_k() {
    int n = blockIdx.x;
    int tid = threadIdx.x;
    float s = 0.f;
    for (int j = tid; j < 512; j += 128) {
        float a = g_ore[n * 512 + j], b = g_oim[n * 512 + j];
        s += a * a + b * b;
    }
    __shared__ float sh[128];
    sh[tid] = s; __syncthreads();
    for (int st = 64; st > 0; st >>= 1) {
        if (tid < st) sh[tid] += sh[tid + st];
        __syncthreads();
    }
    if (tid == 0) g_t[n] = sh[0] * (1.f / 512.f);
}

__global__ void stats_k(float* __restrict__ out) {
    int tid = threadIdx.x;
    float t0 = g_t[tid], t1 = g_t[tid + 1024];
    __shared__ float sh[1024];
    sh[tid] = fmaxf(t0, t1); __syncthreads();
    for (int s = 512; s > 0; s >>= 1) {
        if (tid < s) sh[tid] = fmaxf(sh[tid], sh[tid + s]);
        __syncthreads();
    }
    float mx = sh[0]; __syncthreads();
    sh[tid] = expf(t0 - mx) + expf(t1 - mx); __syncthreads();
    for (int s = 512; s > 0; s >>= 1) {
        if (tid < s) sh[tid] += sh[tid + s];
        __syncthreads();
    }
    float denom = sh[0]; __syncthreads();
    sh[tid] = t0 + t1; __syncthreads();
    for (int s = 512; s > 0; s >>= 1) {
        if (tid < s) sh[tid] += sh[tid + s];
        __syncthreads();
    }
    if (tid == 0) {
        g_stats[0] = mx;
        g_stats[1] = denom;
        out[512] = sh[0] * (1.f / 2048.f);
    }
    g_cv[tid] = 0.f;
}

__global__ void build_cm(const float* __restrict__ h_re, const float* __restrict__ h_im) {
    int idx = blockIdx.x * 256 + threadIdx.x;   // NC * LDT
    int n = idx / LDT;
    int j = idx - n * LDT;
    float v;
    if (j < 512) {
        float a = g_ore[n * 512 + j], b = g_oim[n * 512 + j];
        v = sqrtf(a * a + b * b);
    } else if (j == 512) {
        v = g_t[n];
    } else if (j < GIN) {
        int jj = j - 513;
        float a = h_re[n * 1024 + jj], b = h_im[n * 1024 + jj];
        v = sqrtf(a * a + b * b);
    } else v = 0.f;
    g_cm[idx] = v;
}

__global__ void build_comb(const float* __restrict__ h_re, const float* __restrict__ h_im) {
    int idx = blockIdx.x * 256 + threadIdx.x;   // NC * LDT
    int n = idx / LDT;
    int j = idx - n * LDT;
    float cr, ci;
    if (j < 512) {
        cr = g_ore[n * 512 + j]; ci = g_oim[n * 512 + j];
    } else if (j == 512) {
        cr = g_t[n]; ci = 0.f;
    } else if (j < GIN) {
        int jj = j - 513;
        float rv = g_rr[n * 1024 + jj];
        cr = rv * h_re[n * 1024 + jj];
        ci = rv * h_im[n * 1024 + jj];
    } else { cr = 0.f; ci = 0.f; }
    g_cr[idx] = cr;
    g_ci[idx] = ci;
}

__global__ void fmean_k() {
    int b = blockIdx.x;
    int comp = b >> 3, f = b & 7, d = threadIdx.x;
    const float* src = comp ? g_nim : g_nre;
    float s = 0.f;
    for (int i = 0; i < 256; i++) s += src[(f * 256 + i) * 1024 + d];
    g_fm[(comp * 8 + f) * 1024 + d] = s * (1.f / 256.f);
}

__global__ void gmean_k() {
    int comp = blockIdx.x, d = threadIdx.x;
    float s = 0.f;
    for (int f = 0; f < 8; f++) s += g_fm[(comp * 8 + f) * 1024 + d];
    g_gm[comp * 1024 + d] = s * 0.125f;
}

__global__ void apply_sync(float* __restrict__ out, const int* __restrict__ step) {
    int idx = blockIdx.x * 256 + threadIdx.x;
    int comp = idx >> 21;
    int rem = idx & ((1 << 21) - 1);
    int n = rem >> 10, d = rem & 1023;
    const float* src = comp ? g_nim : g_nre;
    float v = src[rem];
    int f = n >> 8;
    v = 0.85f * v + 0.15f * g_fm[(comp * 8 + f) * 1024 + d];
    if (step[0] > 5 && (n & 255) < 64)
        v = 0.85f * v + 0.15f * g_gm[comp * 1024 + d];
    out[513 + idx] = v;
}

__global__ void wsum_k() {
    int blk = blockIdx.x, tid = threadIdx.x;
    float mx = g_stats[0];
    float inv = 1.f / g_stats[1];
    float a0 = 0.f, a1 = 0.f, a2 = 0.f, a3 = 0.f;
    for (int i = 0; i < 32; i++) {
        int n = blk * 32 + i;
        float w = expf(g_t[n] - mx) * inv;
        a0 += w * g_ore[n * 512 + tid];
        a1 += w * g_ore[n * 512 + 256 + tid];
        a2 += w * g_oim[n * 512 + tid];
        a3 += w * g_oim[n * 512 + 256 + tid];
    }
    atomicAdd(&g_cv[tid], a0);
    atomicAdd(&g_cv[256 + tid], a1);
    atomicAdd(&g_cv[512 + tid], a2);
    atomicAdd(&g_cv[768 + tid], a3);
}

__global__ void pred_k(const float* __restrict__ oh_w, const float* __restrict__ oh_b,
                       float* __restrict__ out) {
    int j = blockIdx.x * 256 + threadIdx.x;
    float acc = 0.f;
    for (int k = 0; k < 1024; k++) acc += g_cv[k] * oh_w[k * 512 + j];
    out[j] = acc + oh_b[j];
}

// ---------------- launch ----------------
extern "C" void kernel_launch(void* const* d_in, const int* in_sizes, int n_in,
                              void* d_out, int out_size) {
    (void)in_sizes; (void)n_in; (void)out_size;
    const float* x     = (const float*)d_in[0];
    const float* h_re  = (const float*)d_in[1];
    const float* h_im  = (const float*)d_in[2];
    const float* ea_wr = (const float*)d_in[3];
    const float* ea_br = (const float*)d_in[4];
    const float* ea_wi = (const float*)d_in[5];
    const float* ea_bi = (const float*)d_in[6];
    const float* eg_wr = (const float*)d_in[7];
    const float* eg_br = (const float*)d_in[8];
    const float* eg_wi = (const float*)d_in[9];
    const float* eg_bi = (const float*)d_in[10];
    const float* gz_w  = (const float*)d_in[11];
    const float* gz_b  = (const float*)d_in[12];
    const float* gr_w  = (const float*)d_in[13];
    const float* gr_b  = (const float*)d_in[14];
    const float* ghr_w = (const float*)d_in[15];
    const float* ghr_b = (const float*)d_in[16];
    const float* ghi_w = (const float*)d_in[17];
    const float* ghi_b = (const float*)d_in[18];
    const float* oh_w  = (const float*)d_in[19];
    const float* oh_b  = (const float*)d_in[20];
    const int*   step  = (const int*)d_in[21];
    float* out = (float*)d_out;

    float *pBreT, *pBimT, *pWT, *pVre, *pVim, *pOre, *pOim, *pCm, *pCr, *pCi, *pZ, *pR, *pNre, *pNim;
    cudaGetSymbolAddress((void**)&pBreT, g_BreT);
    cudaGetSymbolAddress((void**)&pBimT, g_BimT);
    cudaGetSymbolAddress((void**)&pWT,   g_WT);
    cudaGetSymbolAddress((void**)&pVre,  g_vre);
    cudaGetSymbolAddress((void**)&pVim,  g_vim);
    cudaGetSymbolAddress((void**)&pOre,  g_ore);
    cudaGetSymbolAddress((void**)&pOim,  g_oim);
    cudaGetSymbolAddress((void**)&pCm,   g_cm);
    cudaGetSymbolAddress((void**)&pCr,   g_cr);
    cudaGetSymbolAddress((void**)&pCi,   g_ci);
    cudaGetSymbolAddress((void**)&pZ,    g_z);
    cudaGetSymbolAddress((void**)&pR,    g_rr);
    cudaGetSymbolAddress((void**)&pNre,  g_nre);
    cudaGetSymbolAddress((void**)&pNim,  g_nim);

    cudaFuncSetAttribute(gemm_mma<0>, cudaFuncAttributeMaxDynamicSharedMemorySize, SMEM_GEMM_BYTES);
    cudaFuncSetAttribute(gemm_mma<1>, cudaFuncAttributeMaxDynamicSharedMemorySize, SMEM_GEMM_BYTES);
    cudaFuncSetAttribute(gemm_mma<2>, cudaFuncAttributeMaxDynamicSharedMemorySize, SMEM_GEMM_BYTES);

    // weight prep
    transpose_e<<<dim3(64, 16), dim3(32, 8)>>>(ea_wr, ea_wi, eg_wr, eg_wi);
    transpose_w<<<dim3(LDT / 32, 32, 4), dim3(32, 8)>>>(gz_w, gr_w, ghr_w, ghi_w);
    prep_vec<<<512, 128>>>(x, ea_wr, ea_br, ea_wi, ea_bi, eg_wr, eg_br, eg_wi, eg_bi);

    // engine: o_re / o_im   (A = [h_re | h_im] via Ksplit=1024)
    gemm_mma<0><<<dim3(4, 16), 256, SMEM_GEMM_BYTES>>>(
        h_re, h_im, 1024, 1024, pBreT, KENG, KENG, pOre, 512, pVre, nullptr, nullptr);
    gemm_mma<0><<<dim3(4, 16), 256, SMEM_GEMM_BYTES>>>(
        h_re, h_im, 1024, 1024, pBimT, KENG, KENG, pOim, 512, pVim, nullptr, nullptr);

    tension_k<<<2048, 128>>>();
    stats_k<<<1, 1024>>>(out);

    build_cm<<<(NC * LDT) / 256, 256>>>(h_re, h_im);
    gemm_mma<1><<<dim3(8, 16), 256, SMEM_GEMM_BYTES>>>(
        pCm, pCm, LDT, LDT, pWT + 0 * (size_t)DH * LDT, LDT, LDT, pZ, 1024, gz_b, nullptr, nullptr);
    gemm_mma<1><<<dim3(8, 16), 256, SMEM_GEMM_BYTES>>>(
        pCm, pCm, LDT, LDT, pWT + 1 * (size_t)DH * LDT, LDT, LDT, pR, 1024, gr_b, nullptr, nullptr);

    build_comb<<<(NC * LDT) / 256, 256>>>(h_re, h_im);
    gemm_mma<2><<<dim3(8, 16), 256, SMEM_GEMM_BYTES>>>(
        pCr, pCr, LDT, LDT, pWT + 2 * (size_t)DH * LDT, LDT, LDT, pNre, 1024, ghr_b, pZ, h_re);
    gemm_mma<2><<<dim3(8, 16), 256, SMEM_GEMM_BYTES>>>(
        pCi, pCi, LDT, LDT, pWT + 3 * (size_t)DH * LDT, LDT, LDT, pNim, 1024, ghi_b, pZ, h_im);

    fmean_k<<<16, 1024>>>();
    gmean_k<<<2, 1024>>>();
    apply_sync<<<16384, 256>>>(out, step);

    wsum_k<<<64, 256>>>();
    pred_k<<<2, 256>>>(oh_w, oh_b, out);
}

// round 4
// speedup vs baseline: 2.1997x; 1.8331x over previous
#include <cuda_runtime.h>
#include <cuda_bf16.h>
#include <cstdint>
#include <math.h>

#define NC 2048
#define DH 1024
#define DO 512
#define GIN 1537
#define LDT 1600           // GRU K padded to multiple of 64
#define KENG 2048

// ---------------- scratch ----------------
__device__ __nv_bfloat16 g_eAh[NC * KENG], g_eAl[NC * KENG];
__device__ __nv_bfloat16 g_eBh[2][DO * KENG], g_eBl[2][DO * KENG];
__device__ __nv_bfloat16 g_WTh[4][DH * LDT], g_WTl[4][DH * LDT];
__device__ __nv_bfloat16 g_cmh[NC * LDT], g_cml[NC * LDT];
__device__ __nv_bfloat16 g_crh[NC * LDT], g_crl[NC * LDT];
__device__ __nv_bfloat16 g_cih[NC * LDT], g_cil[NC * LDT];
__device__ float g_vre[DO];
__device__ float g_vim[DO];
__device__ float g_ore[NC * DO];
__device__ float g_oim[NC * DO];
__device__ float g_t[NC];
__device__ float g_stats[2];
__device__ float g_z[NC * DH];
__device__ float g_rr[NC * DH];
__device__ float g_nre[NC * DH];
__device__ float g_nim[NC * DH];
__device__ float g_fm[2 * 8 * DH];
__device__ float g_gm[2 * DH];
__device__ float g_cv[2 * DO];

// ---------------- helpers ----------------
__device__ __forceinline__ uint32_t smem_u32(const void* p) {
    uint32_t a;
    asm("{ .reg .u64 t; cvta.to.shared.u64 t, %1; cvt.u32.u64 %0, t; }" : "=r"(a) : "l"(p));
    return a;
}
__device__ __forceinline__ void ldsm4(uint32_t* r, uint32_t addr) {
    asm volatile("ldmatrix.sync.aligned.m8n8.x4.shared.b16 {%0,%1,%2,%3}, [%4];"
                 : "=r"(r[0]), "=r"(r[1]), "=r"(r[2]), "=r"(r[3]) : "r"(addr));
}
__device__ __forceinline__ void mma_bf16(float* d, const uint32_t* a, const uint32_t* b) {
    asm volatile("mma.sync.aligned.m16n8k16.row.col.f32.bf16.bf16.f32 "
                 "{%0,%1,%2,%3}, {%4,%5,%6,%7}, {%8,%9}, {%0,%1,%2,%3};"
                 : "+f"(d[0]), "+f"(d[1]), "+f"(d[2]), "+f"(d[3])
                 : "r"(a[0]), "r"(a[1]), "r"(a[2]), "r"(a[3]), "r"(b[0]), "r"(b[1]));
}
__device__ __forceinline__ void cp16(uint32_t dst, const void* src) {
    asm volatile("cp.async.cg.shared.global [%0], [%1], 16;"
                 :: "r"(dst), "l"(__cvta_generic_to_global(src)));
}
#define CP_COMMIT() asm volatile("cp.async.commit_group;" ::: "memory")
#define CP_WAIT1()  asm volatile("cp.async.wait_group 1;" ::: "memory")

__device__ __forceinline__ void split1(float v, __nv_bfloat16& h, __nv_bfloat16& l) {
    h = __float2bfloat16_rn(v);
    l = __float2bfloat16_rn(v - __bfloat162float(h));
}
__device__ __forceinline__ void split4(float4 v, uint2& h, uint2& l) {
    __nv_bfloat16 bx, by, bz, bw, lx, ly, lz, lw;
    split1(v.x, bx, lx); split1(v.y, by, ly);
    split1(v.z, bz, lz); split1(v.w, bw, lw);
    __nv_bfloat162 h0; h0.x = bx; h0.y = by;
    __nv_bfloat162 h1; h1.x = bz; h1.y = bw;
    __nv_bfloat162 l0; l0.x = lx; l0.y = ly;
    __nv_bfloat162 l1; l1.x = lz; l1.y = lw;
    h.x = *reinterpret_cast<const uint32_t*>(&h0);
    h.y = *reinterpret_cast<const uint32_t*>(&h1);
    l.x = *reinterpret_cast<const uint32_t*>(&l0);
    l.y = *reinterpret_cast<const uint32_t*>(&l1);
}

// ---------------- prep kernels ----------------
__global__ void prep_vec(const float* __restrict__ x,
                         const float* __restrict__ ea_wr, const float* __restrict__ ea_br,
                         const float* __restrict__ ea_wi, const float* __restrict__ ea_bi,
                         const float* __restrict__ eg_wr, const float* __restrict__ eg_br,
                         const float* __restrict__ eg_wi, const float* __restrict__ eg_bi) {
    int j = blockIdx.x;
    int tid = threadIdx.x;
    float sr = 0.f, si = 0.f;
    for (int k = tid; k < 512; k += 128) {
        float xv = x[k];
        int r = k * 512 + j;
        sr += xv * (ea_wr[r] - eg_wr[r]);
        si += xv * (ea_wi[r] - eg_wi[r]);
    }
    __shared__ float shr[128], shi[128];
    shr[tid] = sr; shi[tid] = si;
    __syncthreads();
    for (int s = 64; s > 0; s >>= 1) {
        if (tid < s) { shr[tid] += shr[tid + s]; shi[tid] += shi[tid + s]; }
        __syncthreads();
    }
    if (tid == 0) {
        g_vre[j] = shr[0] + ea_br[j] - ea_bi[j] - eg_br[j] + eg_bi[j];
        g_vim[j] = shi[0] + ea_br[j] + ea_bi[j] - eg_br[j] - eg_bi[j];
    }
}

__global__ void prep_eA(const float* __restrict__ h_re, const float* __restrict__ h_im) {
    int idx = blockIdx.x * 256 + threadIdx.x;   // NC * 512 float4 slots
    int n = idx >> 9;
    int k = (idx & 511) * 4;
    float4 v = (k < 1024)
        ? *reinterpret_cast<const float4*>(h_re + n * 1024 + k)
        : *reinterpret_cast<const float4*>(h_im + n * 1024 + (k - 1024));
    uint2 h, l;
    split4(v, h, l);
    *reinterpret_cast<uint2*>(g_eAh + (size_t)n * KENG + k) = h;
    *reinterpret_cast<uint2*>(g_eAl + (size_t)n * KENG + k) = l;
}

__global__ void transpose_e(const float* __restrict__ ea_wr, const float* __restrict__ ea_wi,
                            const float* __restrict__ eg_wr, const float* __restrict__ eg_wi) {
    __shared__ float tr[32][33], ti[32][33];
    int kb = blockIdx.x * 32, nb = blockIdx.y * 32;
    int tx = threadIdx.x, ty = threadIdx.y;
    for (int i = ty; i < 32; i += 8) {
        int k = kb + i, n = nb + tx;
        float re, im;
        if (k < 1024) {
            int r = (512 + k) * 512 + n;
            re = ea_wr[r] - eg_wr[r];
            im = ea_wi[r] - eg_wi[r];
        } else {
            int r = (k - 512) * 512 + n;
            re = -(ea_wi[r] - eg_wi[r]);
            im = ea_wr[r] - eg_wr[r];
        }
        tr[i][tx] = re; ti[i][tx] = im;
    }
    __syncthreads();
    for (int i = ty; i < 32; i += 8) {
        size_t o = (size_t)(nb + i) * KENG + kb + tx;
        __nv_bfloat16 h, l;
        split1(tr[tx][i], h, l);
        g_eBh[0][o] = h; g_eBl[0][o] = l;
        split1(ti[tx][i], h, l);
        g_eBh[1][o] = h; g_eBl[1][o] = l;
    }
}

__global__ void transpose_w(const float* __restrict__ w0, const float* __restrict__ w1,
                            const float* __restrict__ w2, const float* __restrict__ w3) {
    __shared__ float tile[32][33];
    int z = blockIdx.z;
    const float* src = (z == 0) ? w0 : (z == 1) ? w1 : (z == 2) ? w2 : w3;
    int kb = blockIdx.x * 32, nb = blockIdx.y * 32;
    int tx = threadIdx.x, ty = threadIdx.y;
    for (int i = ty; i < 32; i += 8) {
        int k = kb + i;
        tile[i][tx] = (k < GIN) ? src[(size_t)k * 1024 + nb + tx] : 0.f;
    }
    __syncthreads();
    for (int i = ty; i < 32; i += 8) {
        size_t o = (size_t)(nb + i) * LDT + kb + tx;
        __nv_bfloat16 h, l;
        split1(tile[tx][i], h, l);
        g_WTh[z][o] = h; g_WTl[z][o] = l;
    }
}

// ---------------- mma.sync bf16 GEMM (3-term split, cp.async 2-stage) ----------------
#define SMEM_GEMM_BYTES 131072
template<int EPI>
__global__ void __launch_bounds__(256, 1) gemm_mma(
    const __nv_bfloat16* __restrict__ Ah0, const __nv_bfloat16* __restrict__ Ah1,
    const __nv_bfloat16* __restrict__ Al0, const __nv_bfloat16* __restrict__ Al1,
    const __nv_bfloat16* __restrict__ Bh0, const __nv_bfloat16* __restrict__ Bh1,
    const __nv_bfloat16* __restrict__ Bl0, const __nv_bfloat16* __restrict__ Bl1,
    int lda, int ldb, int K,
    float* __restrict__ C0, float* __restrict__ C1, int ldc,
    const float* __restrict__ vec0, const float* __restrict__ vec1,
    const float* __restrict__ Zp,
    const float* __restrict__ Hp0, const float* __restrict__ Hp1)
{
    extern __shared__ char smem[];
    uint32_t sb = smem_u32(smem);
    const int z = blockIdx.z;
    const __nv_bfloat16* Ah = z ? Ah1 : Ah0;
    const __nv_bfloat16* Al = z ? Al1 : Al0;
    const __nv_bfloat16* Bh = z ? Bh1 : Bh0;
    const __nv_bfloat16* Bl = z ? Bl1 : Bl0;
    float* C = z ? C1 : C0;
    const float* vec = z ? vec1 : vec0;
    const float* Hp = z ? Hp1 : Hp0;

    const int tid = threadIdx.x;
    const int wid = tid >> 5, l = tid & 31;
    const int wm = wid & 1, wn = wid >> 1;
    const int bm = blockIdx.y * 128;
    const int bn = blockIdx.x * 128;

    float acc[4][4][4];
#pragma unroll
    for (int a = 0; a < 4; a++)
#pragma unroll
        for (int b = 0; b < 4; b++)
#pragma unroll
            for (int c = 0; c < 4; c++) acc[a][b][c] = 0.f;

    const int NK = K >> 6;

    auto load_stage = [&](int ch, int stage) {
        const int kc = ch << 6;
        const uint32_t base = sb + (uint32_t)stage * 65536;
#pragma unroll
        for (int j = 0; j < 4; j++) {
            const int within = j * 256 + tid;
            const int row = within >> 3, s = within & 7;
            const uint32_t swz = (uint32_t)((row * 128 + s * 16) ^ ((row & 7) << 4));
            const size_t ao = (size_t)(bm + row) * lda + kc + s * 8;
            const size_t bo = (size_t)(bn + row) * ldb + kc + s * 8;
            cp16(base + swz,         Ah + ao);
            cp16(base + 16384 + swz, Al + ao);
            cp16(base + 32768 + swz, Bh + bo);
            cp16(base + 49152 + swz, Bl + bo);
        }
    };

    auto compute = [&](int stage) {
        const uint32_t base = sb + (uint32_t)stage * 65536;
#pragma unroll
        for (int ks = 0; ks < 4; ks++) {
            uint32_t ah[4][4], alo[4][4], bhq[2][4], blq[2][4];
            const int arow0 = wm * 64 + (l & 15);
            const int akb = ks * 32 + ((l >> 4) << 4);
#pragma unroll
            for (int mi = 0; mi < 4; mi++) {
                int row = arow0 + mi * 16;
                uint32_t ad = base + row * 128 + (akb ^ ((row & 7) << 4));
                ldsm4(ah[mi], ad);
                ldsm4(alo[mi], ad + 16384);
            }
            const int brow0 = wn * 32 + (l & 7) + ((l >> 4) << 3);
            const int bkb = ks * 32 + (((l >> 3) & 1) << 4);
#pragma unroll
            for (int nj = 0; nj < 2; nj++) {
                int row = brow0 + nj * 16;
                uint32_t bd = base + 32768 + row * 128 + (bkb ^ ((row & 7) << 4));
                ldsm4(bhq[nj], bd);
                ldsm4(blq[nj], bd + 16384);
            }
#pragma unroll
            for (int mi = 0; mi < 4; mi++)
#pragma unroll
                for (int ni = 0; ni < 4; ni++) {
                    const uint32_t* bh2 = &bhq[ni >> 1][(ni & 1) * 2];
                    const uint32_t* bl2 = &blq[ni >> 1][(ni & 1) * 2];
                    mma_bf16(acc[mi][ni], ah[mi], bh2);
                    mma_bf16(acc[mi][ni], alo[mi], bh2);
                    mma_bf16(acc[mi][ni], ah[mi], bl2);
                }
        }
    };

    load_stage(0, 0);
    CP_COMMIT();
    if (NK > 1) load_stage(1, 1);
    CP_COMMIT();

    for (int ch = 0; ch < NK; ch++) {
        CP_WAIT1();
        __syncthreads();
        compute(ch & 1);
        __syncthreads();
        if (ch + 2 < NK) load_stage(ch + 2, ch & 1);
        CP_COMMIT();
    }

    const int mr = bm + wm * 64 + (l >> 2);
    const int nc0 = bn + wn * 32 + ((l & 3) << 1);
#pragma unroll
    for (int mi = 0; mi < 4; mi++) {
#pragma unroll
        for (int ni = 0; ni < 4; ni++) {
            int n = nc0 + ni * 8;
            float v0 = vec[n], v1 = vec[n + 1];
#pragma unroll
            for (int hh = 0; hh < 2; hh++) {
                int m = mr + mi * 16 + hh * 8;
                float e0 = acc[mi][ni][hh * 2 + 0] + v0;
                float e1 = acc[mi][ni][hh * 2 + 1] + v1;
                if (EPI == 1) {
                    e0 = 1.f / (1.f + expf(-e0));
                    e1 = 1.f / (1.f + expf(-e1));
                }
                if (EPI == 2) {
                    float c0 = tanhf(e0), c1 = tanhf(e1);
                    float z0 = Zp[(size_t)m * ldc + n], z1 = Zp[(size_t)m * ldc + n + 1];
                    float h0 = Hp[(size_t)m * ldc + n], h1 = Hp[(size_t)m * ldc + n + 1];
                    e0 = (1.f - z0) * h0 + z0 * c0;
                    e1 = (1.f - z1) * h1 + z1 * c1;
                }
                float2 o; o.x = e0; o.y = e1;
                *reinterpret_cast<float2*>(C + (size_t)m * ldc + n) = o;
            }
        }
    }
}

// ---------------- elementwise / reductions ----------------
__global__ void tension_k() {
    int n = blockIdx.x;
    int tid = threadIdx.x;
    float s = 0.f;
    for (int j = tid; j < 512; j += 128) {
        float a = g_ore[n * 512 + j], b = g_oim[n * 512 + j];
        s += a * a + b * b;
    }
    __shared__ float sh[128];
    sh[tid] = s; __syncthreads();
    for (int st = 64; st > 0; st >>= 1) {
        if (tid < st) sh[tid] += sh[tid + st];
        __syncthreads();
    }
    if (tid == 0) g_t[n] = sh[0] * (1.f / 512.f);
}

__global__ void stats_k(float* __restrict__ out) {
    int tid = threadIdx.x;
    float t0 = g_t[tid], t1 = g_t[tid + 1024];
    __shared__ float sh[1024];
    sh[tid] = fmaxf(t0, t1); __syncthreads();
    for (int s = 512; s > 0; s >>= 1) {
        if (tid < s) sh[tid] = fmaxf(sh[tid], sh[tid + s]);
        __syncthreads();
    }
    float mx = sh[0]; __syncthreads();
    sh[tid] = expf(t0 - mx) + expf(t1 - mx); __syncthreads();
    for (int s = 512; s > 0; s >>= 1) {
        if (tid < s) sh[tid] += sh[tid + s];
        __syncthreads();
    }
    float denom = sh[0]; __syncthreads();
    sh[tid] = t0 + t1; __syncthreads();
    for (int s = 512; s > 0; s >>= 1) {
        if (tid < s) sh[tid] += sh[tid + s];
        __syncthreads();
    }
    if (tid == 0) {
        g_stats[0] = mx;
        g_stats[1] = denom;
        out[512] = sh[0] * (1.f / 2048.f);
    }
    g_cv[tid] = 0.f;
}

__global__ void build_cm(const float* __restrict__ h_re, const float* __restrict__ h_im) {
    int idx = blockIdx.x * 256 + threadIdx.x;   // NC * LDT
    int n = idx / LDT;
    int j = idx - n * LDT;
    float v;
    if (j < 512) {
        float a = g_ore[n * 512 + j], b = g_oim[n * 512 + j];
        v = sqrtf(a * a + b * b);
    } else if (j == 512) {
        v = g_t[n];
    } else if (j < GIN) {
        int jj = j - 513;
        float a = h_re[n * 1024 + jj], b = h_im[n * 1024 + jj];
        v = sqrtf(a * a + b * b);
    } else v = 0.f;
    __nv_bfloat16 h, l;
    split1(v, h, l);
    g_cmh[idx] = h; g_cml[idx] = l;
}

__global__ void build_comb(const float* __restrict__ h_re, const float* __restrict__ h_im) {
    int idx = blockIdx.x * 256 + threadIdx.x;   // NC * LDT
    int n = idx / LDT;
    int j = idx - n * LDT;
    float cr, ci;
    if (j < 512) {
        cr = g_ore[n * 512 + j]; ci = g_oim[n * 512 + j];
    } else if (j == 512) {
        cr = g_t[n]; ci = 0.f;
    } else if (j < GIN) {
        int jj = j - 513;
        float rv = g_rr[n * 1024 + jj];
        cr = rv * h_re[n * 1024 + jj];
        ci = rv * h_im[n * 1024 + jj];
    } else { cr = 0.f; ci = 0.f; }
    __nv_bfloat16 h, l;
    split1(cr, h, l);
    g_crh[idx] = h; g_crl[idx] = l;
    split1(ci, h, l);
    g_cih[idx] = h; g_cil[idx] = l;
}

__global__ void fmean_k() {
    int b = blockIdx.x;
    int comp = b >> 3, f = b & 7, d = threadIdx.x;
    const float* src = comp ? g_nim : g_nre;
    float s = 0.f;
    for (int i = 0; i < 256; i++) s += src[(f * 256 + i) * 1024 + d];
    g_fm[(comp * 8 + f) * 1024 + d] = s * (1.f / 256.f);
}

__global__ void gmean_k() {
    int comp = blockIdx.x, d = threadIdx.x;
    float s = 0.f;
    for (int f = 0; f < 8; f++) s += g_fm[(comp * 8 + f) * 1024 + d];
    g_gm[comp * 1024 + d] = s * 0.125f;
}

__global__ void apply_sync(float* __restrict__ out, const int* __restrict__ step) {
    int idx = blockIdx.x * 256 + threadIdx.x;
    int comp = idx >> 21;
    int rem = idx & ((1 << 21) - 1);
    int n = rem >> 10, d = rem & 1023;
    const float* src = comp ? g_nim : g_nre;
    float v = src[rem];
    int f = n >> 8;
    v = 0.85f * v + 0.15f * g_fm[(comp * 8 + f) * 1024 + d];
    if (step[0] > 5 && (n & 255) < 64)
        v = 0.85f * v + 0.15f * g_gm[comp * 1024 + d];
    out[513 + idx] = v;
}

__global__ void wsum_k() {
    int blk = blockIdx.x, tid = threadIdx.x;
    float mx = g_stats[0];
    float inv = 1.f / g_stats[1];
    float a0 = 0.f, a1 = 0.f, a2 = 0.f, a3 = 0.f;
    for (int i = 0; i < 32; i++) {
        int n = blk * 32 + i;
        float w = expf(g_t[n] - mx) * inv;
        a0 += w * g_ore[n * 512 + tid];
        a1 += w * g_ore[n * 512 + 256 + tid];
        a2 += w * g_oim[n * 512 + tid];
        a3 += w * g_oim[n * 512 + 256 + tid];
    }
    atomicAdd(&g_cv[tid], a0);
    atomicAdd(&g_cv[256 + tid], a1);
    atomicAdd(&g_cv[512 + tid], a2);
    atomicAdd(&g_cv[768 + tid], a3);
}

__global__ void pred_k(const float* __restrict__ oh_w, const float* __restrict__ oh_b,
                       float* __restrict__ out) {
    int j = blockIdx.x * 256 + threadIdx.x;
    float acc = 0.f;
    for (int k = 0; k < 1024; k++) acc += g_cv[k] * oh_w[k * 512 + j];
    out[j] = acc + oh_b[j];
}

// ---------------- launch ----------------
extern "C" void kernel_launch(void* const* d_in, const int* in_sizes, int n_in,
                              void* d_out, int out_size) {
    (void)in_sizes; (void)n_in; (void)out_size;
    const float* x     = (const float*)d_in[0];
    const float* h_re  = (const float*)d_in[1];
    const float* h_im  = (const float*)d_in[2];
    const float* ea_wr = (const float*)d_in[3];
    const float* ea_br = (const float*)d_in[4];
    const float* ea_wi = (const float*)d_in[5];
    const float* ea_bi = (const float*)d_in[6];
    const float* eg_wr = (const float*)d_in[7];
    const float* eg_br = (const float*)d_in[8];
    const float* eg_wi = (const float*)d_in[9];
    const float* eg_bi = (const float*)d_in[10];
    const float* gz_w  = (const float*)d_in[11];
    const float* gz_b  = (const float*)d_in[12];
    const float* gr_w  = (const float*)d_in[13];
    const float* gr_b  = (const float*)d_in[14];
    const float* ghr_w = (const float*)d_in[15];
    const float* ghr_b = (const float*)d_in[16];
    const float* ghi_w = (const float*)d_in[17];
    const float* ghi_b = (const float*)d_in[18];
    const float* oh_w  = (const float*)d_in[19];
    const float* oh_b  = (const float*)d_in[20];
    const int*   step  = (const int*)d_in[21];
    float* out = (float*)d_out;

    __nv_bfloat16 *pEAh, *pEAl, *pEBh, *pEBl, *pWTh, *pWTl;
    __nv_bfloat16 *pCmh, *pCml, *pCrh, *pCrl, *pCih, *pCil;
    float *pVre, *pVim, *pOre, *pOim, *pZ, *pRr, *pNre, *pNim;
    cudaGetSymbolAddress((void**)&pEAh, g_eAh);
    cudaGetSymbolAddress((void**)&pEAl, g_eAl);
    cudaGetSymbolAddress((void**)&pEBh, g_eBh);
    cudaGetSymbolAddress((void**)&pEBl, g_eBl);
    cudaGetSymbolAddress((void**)&pWTh, g_WTh);
    cudaGetSymbolAddress((void**)&pWTl, g_WTl);
    cudaGetSymbolAddress((void**)&pCmh, g_cmh);
    cudaGetSymbolAddress((void**)&pCml, g_cml);
    cudaGetSymbolAddress((void**)&pCrh, g_crh);
    cudaGetSymbolAddress((void**)&pCrl, g_crl);
    cudaGetSymbolAddress((void**)&pCih, g_cih);
    cudaGetSymbolAddress((void**)&pCil, g_cil);
    cudaGetSymbolAddress((void**)&pVre, g_vre);
    cudaGetSymbolAddress((void**)&pVim, g_vim);
    cudaGetSymbolAddress((void**)&pOre, g_ore);
    cudaGetSymbolAddress((void**)&pOim, g_oim);
    cudaGetSymbolAddress((void**)&pZ,   g_z);
    cudaGetSymbolAddress((void**)&pRr,  g_rr);
    cudaGetSymbolAddress((void**)&pNre, g_nre);
    cudaGetSymbolAddress((void**)&pNim, g_nim);

    cudaFuncSetAttribute(gemm_mma<0>, cudaFuncAttributeMaxDynamicSharedMemorySize, SMEM_GEMM_BYTES);
    cudaFuncSetAttribute(gemm_mma<1>, cudaFuncAttributeMaxDynamicSharedMemorySize, SMEM_GEMM_BYTES);
    cudaFuncSetAttribute(gemm_mma<2>, cudaFuncAttributeMaxDynamicSharedMemorySize, SMEM_GEMM_BYTES);

    const size_t EB = (size_t)DO * KENG;
    const size_t WB = (size_t)DH * LDT;

    transpose_e<<<dim3(64, 16), dim3(32, 8)>>>(ea_wr, ea_wi, eg_wr, eg_wi);
    transpose_w<<<dim3(LDT / 32, 32, 4), dim3(32, 8)>>>(gz_w, gr_w, ghr_w, ghi_w);
    prep_eA<<<4096, 256>>>(h_re, h_im);
    prep_vec<<<512, 128>>>(x, ea_wr, ea_br, ea_wi, ea_bi, eg_wr, eg_br, eg_wi, eg_bi);

    // engine re/im fused
    gemm_mma<0><<<dim3(4, 16, 2), 256, SMEM_GEMM_BYTES>>>(
        pEAh, pEAh, pEAl, pEAl,
        pEBh, pEBh + EB, pEBl, pEBl + EB,
        KENG, KENG, KENG,
        pOre, pOim, 512,
        pVre, pVim, nullptr, nullptr, nullptr);

    tension_k<<<2048, 128>>>();
    stats_k<<<1, 1024>>>(out);

    build_cm<<<(NC * LDT) / 256, 256>>>(h_re, h_im);
    // GRU z & r fused
    gemm_mma<1><<<dim3(8, 16, 2), 256, SMEM_GEMM_BYTES>>>(
        pCmh, pCmh, pCml, pCml,
        pWTh + 0 * WB, pWTh + 1 * WB, pWTl + 0 * WB, pWTl + 1 * WB,
        LDT, LDT, LDT,
        pZ, pRr, 1024,
        gz_b, gr_b, nullptr, nullptr, nullptr);

    build_comb<<<(NC * LDT) / 256, 256>>>(h_re, h_im);
    // GRU candidates fused
    gemm_mma<2><<<dim3(8, 16, 2), 256, SMEM_GEMM_BYTES>>>(
        pCrh, pCih, pCrl, pCil,
        pWTh + 2 * WB, pWTh + 3 * WB, pWTl + 2 * WB, pWTl + 3 * WB,
        LDT, LDT, LDT,
        pNre, pNim, 1024,
        ghr_b, ghi_b, pZ, h_re, h_im);

    fmean_k<<<16, 1024>>>();
    gmean_k<<<2, 1024>>>();
    apply_sync<<<16384, 256>>>(out, step);

    wsum_k<<<64, 256>>>();
    pred_k<<<2, 256>>>(oh_w, oh_b, out);
}